// round 8
// baseline (speedup 1.0000x reference)
#include <cuda_runtime.h>
#include <cuda_bf16.h>
#include <cstdint>

#define N_NODES 50000
#define N_EDGES 800000
#define IN_FEAT 512
#define HIDDEN  64
#define N_CLASS 16
#define KC      32
#define RB      128   // rows per block in gemm1
#define NCHUNK  (IN_FEAT / KC)

// Scratch (device globals — no allocation allowed)
__device__ float g_h0[N_NODES * HIDDEN];   // x @ W1
__device__ float g_h [N_NODES * HIDDEN];   // A @ h0 + b1 (pre-relu)
__device__ float g_z [N_NODES * N_CLASS];  // relu(h) @ W2
__device__ float g_l [N_NODES * N_CLASS];  // A @ z + b2 (logits)

__device__ __forceinline__ void red_add_v4(float* p, float4 v) {
    asm volatile("red.global.add.v4.f32 [%0], {%1,%2,%3,%4};"
                 :: "l"(p), "f"(v.x), "f"(v.y), "f"(v.z), "f"(v.w)
                 : "memory");
}

// ---------------------------------------------------------------------------
// init_h: g_h <- broadcast b1                       (launch #1)
// ---------------------------------------------------------------------------
__global__ void init_h_kernel(const float* __restrict__ b1) {
    int i = blockIdx.x * blockDim.x + threadIdx.x;
    if (i < N_NODES * HIDDEN) g_h[i] = b1[i & (HIDDEN - 1)];
}

// ---------------------------------------------------------------------------
// init_l halves: g_l <- broadcast b2                (launches #2, #3)
// ---------------------------------------------------------------------------
__global__ void init_l_kernel(const float* __restrict__ b2, int base) {
    int i = base + blockIdx.x * blockDim.x + threadIdx.x;
    if (i < N_NODES * N_CLASS) g_l[i] = b2[i & (N_CLASS - 1)];
}

// ---------------------------------------------------------------------------
// GEMM1: g_h0 = x @ W1   (50000x512 @ 512x64)  -- FFMA2, 32-acc tile
// Block: 128 rows x 64 cols, 128 threads (32 x 4).         (launch #4)
// Thread (tx,ty): row-pairs {2tx,2tx+1} and {64+2tx,64+2tx+1},
//                 cols ty*16 .. ty*16+15.   acc = 32 x u64.
// Per warp-k: 2 spread LDS.64 (4 wf) + 8 broadcast LDS.128 (8 wf)
//             feeding 32 FFMA2  ->  0.375 wf per FFMA2 (was 0.5).
// Double-buffered via register prefetch; 3 CTAs/SM; single wave (391 CTAs).
// ---------------------------------------------------------------------------
__global__ __launch_bounds__(128)
void gemm1_kernel(const float* __restrict__ x, const float* __restrict__ W1) {
    __shared__ __align__(16) float  xs[2][KC][RB];       // 32 KB
    __shared__ __align__(16) float2 wd[2][KC][HIDDEN];   // 32 KB

    const int tx  = threadIdx.x;            // 0..31
    const int ty  = threadIdx.y;             // 0..3
    const int tid = ty * 32 + tx;            // 0..127
    const int row0 = blockIdx.x * RB;

    // x staging: one thread per row, 32 k-values (8 float4)
    int grow = row0 + tid;
    if (grow >= N_NODES) grow = N_NODES - 1;   // clamp; masked at output
    const float* xrow = x + (size_t)grow * IN_FEAT;
    // W staging: 4 float4 per thread (512 float4 per chunk)
    const int wkk = tid >> 4;                 // base k (0..7), +8 per j
    const int wqq = tid & 15;                 // float4 within 64-col row

    float4 xr[8];
    float4 wr[4];

    auto ld = [&](int c) {
        const int k0 = c * KC;
        #pragma unroll
        for (int q = 0; q < 8; q++)
            xr[q] = __ldg(reinterpret_cast<const float4*>(&xrow[k0 + q * 4]));
        #pragma unroll
        for (int j = 0; j < 4; j++)
            wr[j] = __ldg(reinterpret_cast<const float4*>(
                        &W1[(size_t)(k0 + wkk + j * 8) * HIDDEN + wqq * 4]));
    };
    auto st = [&](int b) {
        #pragma unroll
        for (int q = 0; q < 8; q++) {
            xs[b][q * 4 + 0][tid] = xr[q].x;
            xs[b][q * 4 + 1][tid] = xr[q].y;
            xs[b][q * 4 + 2][tid] = xr[q].z;
            xs[b][q * 4 + 3][tid] = xr[q].w;
        }
        #pragma unroll
        for (int j = 0; j < 4; j++) {
            float2* wp = &wd[b][wkk + j * 8][wqq * 4];
            wp[0] = make_float2(wr[j].x, wr[j].x);
            wp[1] = make_float2(wr[j].y, wr[j].y);
            wp[2] = make_float2(wr[j].z, wr[j].z);
            wp[3] = make_float2(wr[j].w, wr[j].w);
        }
    };

    unsigned long long acc0[16] = {};   // rows {2tx, 2tx+1},     16 cols
    unsigned long long acc1[16] = {};   // rows {64+2tx, 64+2tx+1}

    ld(0); st(0);
    __syncthreads();

    for (int c = 0; c < NCHUNK; c++) {
        const int cb = c & 1;
        if (c + 1 < NCHUNK) ld(c + 1);          // LDGs overlap compute

        #pragma unroll
        for (int k = 0; k < KC; k++) {
            unsigned long long xp0 =
                *reinterpret_cast<const unsigned long long*>(&xs[cb][k][2 * tx]);
            unsigned long long xp1 =
                *reinterpret_cast<const unsigned long long*>(&xs[cb][k][64 + 2 * tx]);
            const ulonglong2* wrow =
                reinterpret_cast<const ulonglong2*>(&wd[cb][k][ty * 16]);
            #pragma unroll
            for (int q = 0; q < 8; q++) {
                ulonglong2 w2 = wrow[q];      // cols 2q,2q+1 (dup'd), broadcast
                asm("fma.rn.f32x2 %0, %1, %2, %0;" : "+l"(acc0[2*q])   : "l"(xp0), "l"(w2.x));
                asm("fma.rn.f32x2 %0, %1, %2, %0;" : "+l"(acc0[2*q+1]) : "l"(xp0), "l"(w2.y));
                asm("fma.rn.f32x2 %0, %1, %2, %0;" : "+l"(acc1[2*q])   : "l"(xp1), "l"(w2.x));
                asm("fma.rn.f32x2 %0, %1, %2, %0;" : "+l"(acc1[2*q+1]) : "l"(xp1), "l"(w2.y));
            }
        }

        if (c + 1 < NCHUNK) st((c + 1) & 1);    // other buffer: safe pre-sync
        __syncthreads();
    }

    // Epilogue: unpack row-pairs, write 16 cols per thread
    #pragma unroll
    for (int i = 0; i < 2; i++) {
        const unsigned long long* a = (i == 0) ? acc0 : acc1;
        int r = row0 + i * 64 + tx * 2;
        float lo[16], hi[16];
        #pragma unroll
        for (int c = 0; c < 16; c++) {
            float2 f = *reinterpret_cast<const float2*>(&a[c]);
            lo[c] = f.x; hi[c] = f.y;
        }
        if (r < N_NODES) {
            float4* o = reinterpret_cast<float4*>(&g_h0[(size_t)r * HIDDEN + ty * 16]);
            #pragma unroll
            for (int q = 0; q < 4; q++)
                o[q] = make_float4(lo[q*4], lo[q*4+1], lo[q*4+2], lo[q*4+3]);
        }
        if (r + 1 < N_NODES) {
            float4* o = reinterpret_cast<float4*>(&g_h0[(size_t)(r + 1) * HIDDEN + ty * 16]);
            #pragma unroll
            for (int q = 0; q < 4; q++)
                o[q] = make_float4(hi[q*4], hi[q*4+1], hi[q*4+2], hi[q*4+3]);
        }
    }
}

// ---------------------------------------------------------------------------
// SpMM1: g_h[dst] += ew * g_h0[src]   (64 feats, 16 lanes/edge, float4 RED)
// ---------------------------------------------------------------------------
__global__ __launch_bounds__(256)
void spmm1_kernel(const int* __restrict__ src, const int* __restrict__ dst,
                  const float* __restrict__ ew) {
    int t = blockIdx.x * blockDim.x + threadIdx.x;
    int e = t >> 4;
    int f = (t & 15) << 2;
    if (e >= N_EDGES) return;
    int s   = __ldg(&src[e]);
    int d   = __ldg(&dst[e]);
    float w = __ldg(&ew[e]);
    float4 v = *reinterpret_cast<const float4*>(&g_h0[(size_t)s * HIDDEN + f]);
    red_add_v4(&g_h[(size_t)d * HIDDEN + f],
               make_float4(v.x * w, v.y * w, v.z * w, v.w * w));
}

// ---------------------------------------------------------------------------
// GEMM2: g_z = relu(g_h) @ W2   (50000x64 @ 64x16), thread per node.
// ---------------------------------------------------------------------------
__global__ __launch_bounds__(64)
void gemm2_kernel(const float* __restrict__ W2) {
    __shared__ float4 Ws[HIDDEN][N_CLASS / 4];   // 4 KB

    const int tid = threadIdx.x;
    #pragma unroll
    for (int j = 0; j < 4; j++) {
        int i = tid + j * 64;
        int kk = i >> 2, qq = i & 3;
        Ws[kk][qq] = reinterpret_cast<const float4*>(&W2[(size_t)kk * N_CLASS])[qq];
    }
    __syncthreads();

    int n = blockIdx.x * 64 + tid;
    if (n >= N_NODES) return;

    float acc[N_CLASS] = {};
    const float4* hrow = reinterpret_cast<const float4*>(&g_h[(size_t)n * HIDDEN]);
    #pragma unroll
    for (int kq = 0; kq < HIDDEN / 4; kq++) {
        float4 h4 = __ldg(&hrow[kq]);
        float hv[4] = {fmaxf(h4.x, 0.f), fmaxf(h4.y, 0.f),
                       fmaxf(h4.z, 0.f), fmaxf(h4.w, 0.f)};
        #pragma unroll
        for (int j = 0; j < 4; j++) {
            int k = kq * 4 + j;
            #pragma unroll
            for (int q = 0; q < 4; q++) {
                float4 w4 = Ws[k][q];
                acc[q * 4 + 0] = fmaf(hv[j], w4.x, acc[q * 4 + 0]);
                acc[q * 4 + 1] = fmaf(hv[j], w4.y, acc[q * 4 + 1]);
                acc[q * 4 + 2] = fmaf(hv[j], w4.z, acc[q * 4 + 2]);
                acc[q * 4 + 3] = fmaf(hv[j], w4.w, acc[q * 4 + 3]);
            }
        }
    }
    float4* o = reinterpret_cast<float4*>(&g_z[(size_t)n * N_CLASS]);
    #pragma unroll
    for (int q = 0; q < 4; q++)
        o[q] = make_float4(acc[q * 4], acc[q * 4 + 1], acc[q * 4 + 2], acc[q * 4 + 3]);
}

// ---------------------------------------------------------------------------
// SpMM2: g_l[dst] += ew * g_z[src]   (16 classes, 4 lanes/edge, float4 RED)
// ---------------------------------------------------------------------------
__global__ __launch_bounds__(256)
void spmm2_kernel(const int* __restrict__ src, const int* __restrict__ dst,
                  const float* __restrict__ ew) {
    int t = blockIdx.x * blockDim.x + threadIdx.x;
    int e = t >> 2;
    int c = (t & 3) << 2;
    if (e >= N_EDGES) return;
    int s   = __ldg(&src[e]);
    int d   = __ldg(&dst[e]);
    float w = __ldg(&ew[e]);
    float4 v = *reinterpret_cast<const float4*>(&g_z[(size_t)s * N_CLASS + c]);
    red_add_v4(&g_l[(size_t)d * N_CLASS + c],
               make_float4(v.x * w, v.y * w, v.z * w, v.w * w));
}

// ---------------------------------------------------------------------------
// Softmax over 16 classes, one thread per node.
// ---------------------------------------------------------------------------
__global__ __launch_bounds__(256)
void softmax_kernel(float* __restrict__ out) {
    int n = blockIdx.x * blockDim.x + threadIdx.x;
    if (n >= N_NODES) return;
    float v[N_CLASS];
    const float4* p = reinterpret_cast<const float4*>(&g_l[(size_t)n * N_CLASS]);
    #pragma unroll
    for (int i = 0; i < 4; i++) {
        float4 q = p[i];
        v[i * 4 + 0] = q.x; v[i * 4 + 1] = q.y; v[i * 4 + 2] = q.z; v[i * 4 + 3] = q.w;
    }
    float m = v[0];
    #pragma unroll
    for (int i = 1; i < N_CLASS; i++) m = fmaxf(m, v[i]);
    float sum = 0.f;
    #pragma unroll
    for (int i = 0; i < N_CLASS; i++) { v[i] = __expf(v[i] - m); sum += v[i]; }
    float inv = 1.f / sum;
    float4* o = reinterpret_cast<float4*>(&out[(size_t)n * N_CLASS]);
    #pragma unroll
    for (int i = 0; i < 4; i++) {
        o[i] = make_float4(v[i * 4] * inv, v[i * 4 + 1] * inv,
                           v[i * 4 + 2] * inv, v[i * 4 + 3] * inv);
    }
}

// ---------------------------------------------------------------------------
extern "C" void kernel_launch(void* const* d_in, const int* in_sizes, int n_in,
                              void* d_out, int out_size) {
    const float* x   = (const float*)d_in[0];
    const int*   src = (const int*)  d_in[1];
    const int*   dst = (const int*)  d_in[2];
    const float* ew  = (const float*)d_in[3];
    const float* W1  = (const float*)d_in[4];
    const float* b1  = (const float*)d_in[5];
    const float* W2  = (const float*)d_in[6];
    const float* b2  = (const float*)d_in[7];
    float* out = (float*)d_out;

    const int HALF_L = (N_NODES * N_CLASS) / 2;

    // #1..#3: bias broadcasts (3 launches so gemm1 lands at profiled slot #4)
    init_h_kernel<<<(N_NODES * HIDDEN + 255) / 256, 256>>>(b1);
    init_l_kernel<<<(HALF_L + 255) / 256, 256>>>(b2, 0);
    init_l_kernel<<<(HALF_L + 255) / 256, 256>>>(b2, HALF_L);

    // #4  (profiled)
    gemm1_kernel<<<(N_NODES + RB - 1) / RB, dim3(32, 4)>>>(x, W1);

    // #5
    {
        long long threads = (long long)N_EDGES * 16;
        spmm1_kernel<<<(unsigned)((threads + 255) / 256), 256>>>(src, dst, ew);
    }
    // #6
    gemm2_kernel<<<(N_NODES + 63) / 64, 64>>>(W2);
    // #7
    {
        long long threads = (long long)N_EDGES * 4;
        spmm2_kernel<<<(unsigned)((threads + 255) / 256), 256>>>(src, dst, ew);
    }
    // #8
    softmax_kernel<<<(N_NODES + 255) / 256, 256>>>(out);
}

// round 9
// speedup vs baseline: 1.3538x; 1.3538x over previous
#include <cuda_runtime.h>
#include <cuda_bf16.h>
#include <cstdint>

#define N_NODES 50000
#define N_EDGES 800000
#define IN_FEAT 512
#define HIDDEN  64
#define N_CLASS 16

#define KC2   32                    // K per chunk (bf16 path)
#define KPAD  40                    // padded row length (80B stride, conflict-free frags)
#define RBM   128                   // rows per CTA in gemm1
#define NCHUNK2 (IN_FEAT / KC2)     // 16

// Scratch (device globals — no allocation allowed)
__device__ float g_h0[N_NODES * HIDDEN];   // x @ W1
__device__ float g_h [N_NODES * HIDDEN];   // A @ h0 + b1 (pre-relu)
__device__ float g_z [N_NODES * N_CLASS];  // relu(h) @ W2
__device__ float g_l [N_NODES * N_CLASS];  // A @ z + b2 (logits)
__device__ __nv_bfloat16 g_w1t_hi[HIDDEN * IN_FEAT];  // W1^T hi, [n][k]
__device__ __nv_bfloat16 g_w1t_lo[HIDDEN * IN_FEAT];  // W1^T residual

__device__ __forceinline__ void red_add_v4(float* p, float4 v) {
    asm volatile("red.global.add.v4.f32 [%0], {%1,%2,%3,%4};"
                 :: "l"(p), "f"(v.x), "f"(v.y), "f"(v.z), "f"(v.w)
                 : "memory");
}

// pack two floats to bf16x2: low 16 bits = v0, high = v1
__device__ __forceinline__ uint32_t pack_bf2(float v0, float v1) {
    uint32_t r;
    asm("cvt.rn.bf16x2.f32 %0, %1, %2;" : "=r"(r) : "f"(v1), "f"(v0));
    return r;
}
__device__ __forceinline__ float bf_round(float v) {
    return __bfloat162float(__float2bfloat16_rn(v));
}

__device__ __forceinline__ void mma_bf16(float* d, const uint32_t* a,
                                         uint32_t b0, uint32_t b1) {
    asm("mma.sync.aligned.m16n8k16.row.col.f32.bf16.bf16.f32 "
        "{%0,%1,%2,%3}, {%4,%5,%6,%7}, {%8,%9}, {%0,%1,%2,%3};"
        : "+f"(d[0]), "+f"(d[1]), "+f"(d[2]), "+f"(d[3])
        : "r"(a[0]), "r"(a[1]), "r"(a[2]), "r"(a[3]), "r"(b0), "r"(b1));
}

// ---------------------------------------------------------------------------
// init_h: g_h <- broadcast b1                       (launch #1)
// ---------------------------------------------------------------------------
__global__ void init_h_kernel(const float* __restrict__ b1) {
    int i = blockIdx.x * blockDim.x + threadIdx.x;
    if (i < N_NODES * HIDDEN) g_h[i] = b1[i & (HIDDEN - 1)];
}

// ---------------------------------------------------------------------------
// init_l: g_l <- broadcast b2                       (launch #2)
// ---------------------------------------------------------------------------
__global__ void init_l_kernel(const float* __restrict__ b2) {
    int i = blockIdx.x * blockDim.x + threadIdx.x;
    if (i < N_NODES * N_CLASS) g_l[i] = b2[i & (N_CLASS - 1)];
}

// ---------------------------------------------------------------------------
// w1t: W1[k][n] fp32 -> g_w1t_{hi,lo}[n][k] bf16    (launch #3)
// ---------------------------------------------------------------------------
__global__ void w1t_kernel(const float* __restrict__ W1) {
    int i = blockIdx.x * blockDim.x + threadIdx.x;
    if (i >= IN_FEAT * HIDDEN) return;
    int k = i >> 6;
    int n = i & 63;
    float v = W1[i];
    __nv_bfloat16 h = __float2bfloat16_rn(v);
    float r = v - __bfloat162float(h);
    g_w1t_hi[(size_t)n * IN_FEAT + k] = h;
    g_w1t_lo[(size_t)n * IN_FEAT + k] = __float2bfloat16_rn(r);
}

// ---------------------------------------------------------------------------
// GEMM1: g_h0 = x @ W1  via mma.sync bf16 (3-term split)   (launch #4)
// CTA: 256 thr = 8 warps. Tile M=128, N=64. Warp w: rows w*16..w*16+15.
// Per k16 step: a-frags (hi+lo) loaded once, 8 n-tiles x 3 mma.
// Smem rows padded to KPAD=40 bf16 (80B): fragment LDS conflict-free.
// ---------------------------------------------------------------------------
__global__ __launch_bounds__(256, 3)
void gemm1_kernel(const float* __restrict__ x) {
    __shared__ __align__(16) __nv_bfloat16 Ah[RBM * KPAD];     // 10 KB
    __shared__ __align__(16) __nv_bfloat16 Al[RBM * KPAD];     // 10 KB
    __shared__ __align__(16) __nv_bfloat16 Bh[HIDDEN * KPAD];  // 5 KB
    __shared__ __align__(16) __nv_bfloat16 Bl[HIDDEN * KPAD];  // 5 KB

    const int tid  = threadIdx.x;
    const int wid  = tid >> 5;
    const int lane = tid & 31;
    const int g    = lane >> 2;       // 0..7
    const int tig  = lane & 3;        // 0..3
    const int row0 = blockIdx.x * RBM;

    // x staging: 2 threads per row; thread stages 16 k-values
    const int strow  = tid >> 1;
    const int sthalf = tid & 1;
    int grow = row0 + strow;
    if (grow >= N_NODES) grow = N_NODES - 1;   // clamp; masked at store
    const float* xrow = x + (size_t)grow * IN_FEAT + sthalf * 16;

    // B staging: 256 16B segments per buffer pair; thread does 1 hi + 1 lo
    const int bn  = tid >> 2;          // 0..63
    const int bsg = tid & 3;           // 0..3 (8 bf16 each)

    float d[8][4] = {};                // 8 n-tiles x 4 accum

    for (int c = 0; c < NCHUNK2; c++) {
        const int k0 = c * KC2;

        // --- stage A (convert fp32 -> bf16 hi/lo) ---
        #pragma unroll
        for (int q = 0; q < 4; q++) {
            float4 v = __ldg(reinterpret_cast<const float4*>(&xrow[k0 + q * 4]));
            uint32_t h01 = pack_bf2(v.x, v.y);
            uint32_t h23 = pack_bf2(v.z, v.w);
            uint32_t l01 = pack_bf2(v.x - bf_round(v.x), v.y - bf_round(v.y));
            uint32_t l23 = pack_bf2(v.z - bf_round(v.z), v.w - bf_round(v.w));
            int eo = strow * KPAD + sthalf * 16 + q * 4;
            *reinterpret_cast<uint32_t*>(&Ah[eo])     = h01;
            *reinterpret_cast<uint32_t*>(&Ah[eo + 2]) = h23;
            *reinterpret_cast<uint32_t*>(&Al[eo])     = l01;
            *reinterpret_cast<uint32_t*>(&Al[eo + 2]) = l23;
        }
        // --- stage B (copy pre-split W1^T) ---
        {
            uint4 wh = *reinterpret_cast<const uint4*>(
                           &g_w1t_hi[(size_t)bn * IN_FEAT + k0 + bsg * 8]);
            uint4 wl = *reinterpret_cast<const uint4*>(
                           &g_w1t_lo[(size_t)bn * IN_FEAT + k0 + bsg * 8]);
            *reinterpret_cast<uint4*>(&Bh[bn * KPAD + bsg * 8]) = wh;
            *reinterpret_cast<uint4*>(&Bl[bn * KPAD + bsg * 8]) = wl;
        }
        __syncthreads();

        // --- compute: 2 k16 steps ---
        #pragma unroll
        for (int ks = 0; ks < 2; ks++) {
            const int abase = (wid * 16 + g) * KPAD + ks * 16 + 2 * tig;
            uint32_t ah[4], al[4];
            ah[0] = *reinterpret_cast<const uint32_t*>(&Ah[abase]);
            ah[1] = *reinterpret_cast<const uint32_t*>(&Ah[abase + 8 * KPAD]);
            ah[2] = *reinterpret_cast<const uint32_t*>(&Ah[abase + 8]);
            ah[3] = *reinterpret_cast<const uint32_t*>(&Ah[abase + 8 * KPAD + 8]);
            al[0] = *reinterpret_cast<const uint32_t*>(&Al[abase]);
            al[1] = *reinterpret_cast<const uint32_t*>(&Al[abase + 8 * KPAD]);
            al[2] = *reinterpret_cast<const uint32_t*>(&Al[abase + 8]);
            al[3] = *reinterpret_cast<const uint32_t*>(&Al[abase + 8 * KPAD + 8]);
            #pragma unroll
            for (int nt = 0; nt < 8; nt++) {
                const int bbase = (nt * 8 + g) * KPAD + ks * 16 + 2 * tig;
                uint32_t bh0 = *reinterpret_cast<const uint32_t*>(&Bh[bbase]);
                uint32_t bh1 = *reinterpret_cast<const uint32_t*>(&Bh[bbase + 8]);
                uint32_t bl0 = *reinterpret_cast<const uint32_t*>(&Bl[bbase]);
                uint32_t bl1 = *reinterpret_cast<const uint32_t*>(&Bl[bbase + 8]);
                mma_bf16(d[nt], ah, bh0, bh1);
                mma_bf16(d[nt], al, bh0, bh1);
                mma_bf16(d[nt], ah, bl0, bl1);
            }
        }
        __syncthreads();
    }

    // Epilogue: d0,d1 -> row (wid*16+g), cols nt*8+2tig..+1 ; d2,d3 -> row+8
    {
        int r0 = row0 + wid * 16 + g;
        int r1 = r0 + 8;
        #pragma unroll
        for (int nt = 0; nt < 8; nt++) {
            int col = nt * 8 + 2 * tig;
            if (r0 < N_NODES)
                *reinterpret_cast<float2*>(&g_h0[(size_t)r0 * HIDDEN + col]) =
                    make_float2(d[nt][0], d[nt][1]);
            if (r1 < N_NODES)
                *reinterpret_cast<float2*>(&g_h0[(size_t)r1 * HIDDEN + col]) =
                    make_float2(d[nt][2], d[nt][3]);
        }
    }
}

// ---------------------------------------------------------------------------
// SpMM1: g_h[dst] += ew * g_h0[src]   (64 feats, 16 lanes/edge, float4 RED)
// ---------------------------------------------------------------------------
__global__ __launch_bounds__(256)
void spmm1_kernel(const int* __restrict__ src, const int* __restrict__ dst,
                  const float* __restrict__ ew) {
    int t = blockIdx.x * blockDim.x + threadIdx.x;
    int e = t >> 4;
    int f = (t & 15) << 2;
    if (e >= N_EDGES) return;
    int s   = __ldg(&src[e]);
    int d   = __ldg(&dst[e]);
    float w = __ldg(&ew[e]);
    float4 v = *reinterpret_cast<const float4*>(&g_h0[(size_t)s * HIDDEN + f]);
    red_add_v4(&g_h[(size_t)d * HIDDEN + f],
               make_float4(v.x * w, v.y * w, v.z * w, v.w * w));
}

// ---------------------------------------------------------------------------
// GEMM2: g_z = relu(g_h) @ W2   (50000x64 @ 64x16), thread per node.
// ---------------------------------------------------------------------------
__global__ __launch_bounds__(64)
void gemm2_kernel(const float* __restrict__ W2) {
    __shared__ float4 Ws[HIDDEN][N_CLASS / 4];   // 4 KB

    const int tid = threadIdx.x;
    #pragma unroll
    for (int j = 0; j < 4; j++) {
        int i = tid + j * 64;
        int kk = i >> 2, qq = i & 3;
        Ws[kk][qq] = reinterpret_cast<const float4*>(&W2[(size_t)kk * N_CLASS])[qq];
    }
    __syncthreads();

    int n = blockIdx.x * 64 + tid;
    if (n >= N_NODES) return;

    float acc[N_CLASS] = {};
    const float4* hrow = reinterpret_cast<const float4*>(&g_h[(size_t)n * HIDDEN]);
    #pragma unroll
    for (int kq = 0; kq < HIDDEN / 4; kq++) {
        float4 h4 = __ldg(&hrow[kq]);
        float hv[4] = {fmaxf(h4.x, 0.f), fmaxf(h4.y, 0.f),
                       fmaxf(h4.z, 0.f), fmaxf(h4.w, 0.f)};
        #pragma unroll
        for (int j = 0; j < 4; j++) {
            int k = kq * 4 + j;
            #pragma unroll
            for (int q = 0; q < 4; q++) {
                float4 w4 = Ws[k][q];
                acc[q * 4 + 0] = fmaf(hv[j], w4.x, acc[q * 4 + 0]);
                acc[q * 4 + 1] = fmaf(hv[j], w4.y, acc[q * 4 + 1]);
                acc[q * 4 + 2] = fmaf(hv[j], w4.z, acc[q * 4 + 2]);
                acc[q * 4 + 3] = fmaf(hv[j], w4.w, acc[q * 4 + 3]);
            }
        }
    }
    float4* o = reinterpret_cast<float4*>(&g_z[(size_t)n * N_CLASS]);
    #pragma unroll
    for (int q = 0; q < 4; q++)
        o[q] = make_float4(acc[q * 4], acc[q * 4 + 1], acc[q * 4 + 2], acc[q * 4 + 3]);
}

// ---------------------------------------------------------------------------
// SpMM2: g_l[dst] += ew * g_z[src]   (16 classes, 4 lanes/edge, float4 RED)
// ---------------------------------------------------------------------------
__global__ __launch_bounds__(256)
void spmm2_kernel(const int* __restrict__ src, const int* __restrict__ dst,
                  const float* __restrict__ ew) {
    int t = blockIdx.x * blockDim.x + threadIdx.x;
    int e = t >> 2;
    int c = (t & 3) << 2;
    if (e >= N_EDGES) return;
    int s   = __ldg(&src[e]);
    int d   = __ldg(&dst[e]);
    float w = __ldg(&ew[e]);
    float4 v = *reinterpret_cast<const float4*>(&g_z[(size_t)s * N_CLASS + c]);
    red_add_v4(&g_l[(size_t)d * N_CLASS + c],
               make_float4(v.x * w, v.y * w, v.z * w, v.w * w));
}

// ---------------------------------------------------------------------------
// Softmax over 16 classes, one thread per node.
// ---------------------------------------------------------------------------
__global__ __launch_bounds__(256)
void softmax_kernel(float* __restrict__ out) {
    int n = blockIdx.x * blockDim.x + threadIdx.x;
    if (n >= N_NODES) return;
    float v[N_CLASS];
    const float4* p = reinterpret_cast<const float4*>(&g_l[(size_t)n * N_CLASS]);
    #pragma unroll
    for (int i = 0; i < 4; i++) {
        float4 q = p[i];
        v[i * 4 + 0] = q.x; v[i * 4 + 1] = q.y; v[i * 4 + 2] = q.z; v[i * 4 + 3] = q.w;
    }
    float m = v[0];
    #pragma unroll
    for (int i = 1; i < N_CLASS; i++) m = fmaxf(m, v[i]);
    float sum = 0.f;
    #pragma unroll
    for (int i = 0; i < N_CLASS; i++) { v[i] = __expf(v[i] - m); sum += v[i]; }
    float inv = 1.f / sum;
    float4* o = reinterpret_cast<float4*>(&out[(size_t)n * N_CLASS]);
    #pragma unroll
    for (int i = 0; i < 4; i++) {
        o[i] = make_float4(v[i * 4] * inv, v[i * 4 + 1] * inv,
                           v[i * 4 + 2] * inv, v[i * 4 + 3] * inv);
    }
}

// ---------------------------------------------------------------------------
extern "C" void kernel_launch(void* const* d_in, const int* in_sizes, int n_in,
                              void* d_out, int out_size) {
    const float* x   = (const float*)d_in[0];
    const int*   src = (const int*)  d_in[1];
    const int*   dst = (const int*)  d_in[2];
    const float* ew  = (const float*)d_in[3];
    const float* W1  = (const float*)d_in[4];
    const float* b1  = (const float*)d_in[5];
    const float* W2  = (const float*)d_in[6];
    const float* b2  = (const float*)d_in[7];
    float* out = (float*)d_out;

    // #1, #2: bias broadcasts
    init_h_kernel<<<(N_NODES * HIDDEN + 255) / 256, 256>>>(b1);
    init_l_kernel<<<(N_NODES * N_CLASS + 255) / 256, 256>>>(b2);
    // #3: W1 transpose + bf16 split
    w1t_kernel<<<(IN_FEAT * HIDDEN + 255) / 256, 256>>>(W1);

    // #4  (profiled slot)
    gemm1_kernel<<<(N_NODES + RBM - 1) / RBM, 256>>>(x);

    // #5
    {
        long long threads = (long long)N_EDGES * 16;
        spmm1_kernel<<<(unsigned)((threads + 255) / 256), 256>>>(src, dst, ew);
    }
    // #6
    gemm2_kernel<<<(N_NODES + 63) / 64, 64>>>(W2);
    // #7
    {
        long long threads = (long long)N_EDGES * 4;
        spmm2_kernel<<<(unsigned)((threads + 255) / 256), 256>>>(src, dst, ew);
    }
    // #8
    softmax_kernel<<<(N_NODES + 255) / 256, 256>>>(out);
}

// round 10
// speedup vs baseline: 1.3633x; 1.0070x over previous
#include <cuda_runtime.h>
#include <cuda_bf16.h>
#include <cstdint>

#define N_NODES 50000
#define N_EDGES 800000
#define IN_FEAT 512
#define HIDDEN  64
#define N_CLASS 16

#define KC2   32                    // K per chunk
#define KPAD  40                    // padded row (80B stride -> conflict-free frags)
#define RBM   64                    // rows per CTA in gemm1
#define NCHUNK2 (IN_FEAT / KC2)     // 16

// Scratch (device globals — no allocation allowed)
__device__ float g_h0[N_NODES * HIDDEN];   // x @ W1
__device__ float g_h [N_NODES * HIDDEN];   // A @ h0 + b1 (pre-relu)
__device__ float g_z [N_NODES * N_CLASS];  // relu(h) @ W2
__device__ float g_l [N_NODES * N_CLASS];  // A @ z + b2 (logits)
__device__ __nv_bfloat16 g_w1t_hi[HIDDEN * IN_FEAT];  // W1^T hi, [n][k]
__device__ __nv_bfloat16 g_w1t_lo[HIDDEN * IN_FEAT];  // W1^T residual

__device__ __forceinline__ void red_add_v4(float* p, float4 v) {
    asm volatile("red.global.add.v4.f32 [%0], {%1,%2,%3,%4};"
                 :: "l"(p), "f"(v.x), "f"(v.y), "f"(v.z), "f"(v.w)
                 : "memory");
}

__device__ __forceinline__ uint32_t pack_bf2(float v0, float v1) {
    uint32_t r;
    asm("cvt.rn.bf16x2.f32 %0, %1, %2;" : "=r"(r) : "f"(v1), "f"(v0));
    return r;
}
__device__ __forceinline__ float bf_round(float v) {
    return __bfloat162float(__float2bfloat16_rn(v));
}

__device__ __forceinline__ void mma_bf16(float* d, const uint32_t* a,
                                         uint32_t b0, uint32_t b1) {
    asm("mma.sync.aligned.m16n8k16.row.col.f32.bf16.bf16.f32 "
        "{%0,%1,%2,%3}, {%4,%5,%6,%7}, {%8,%9}, {%0,%1,%2,%3};"
        : "+f"(d[0]), "+f"(d[1]), "+f"(d[2]), "+f"(d[3])
        : "r"(a[0]), "r"(a[1]), "r"(a[2]), "r"(a[3]), "r"(b0), "r"(b1));
}

// ---------------------------------------------------------------------------
// init_h: g_h <- broadcast b1                       (launch #1)
// ---------------------------------------------------------------------------
__global__ void init_h_kernel(const float* __restrict__ b1) {
    int i = blockIdx.x * blockDim.x + threadIdx.x;
    if (i < N_NODES * HIDDEN) g_h[i] = b1[i & (HIDDEN - 1)];
}

// ---------------------------------------------------------------------------
// init_l: g_l <- broadcast b2                       (launch #2)
// ---------------------------------------------------------------------------
__global__ void init_l_kernel(const float* __restrict__ b2) {
    int i = blockIdx.x * blockDim.x + threadIdx.x;
    if (i < N_NODES * N_CLASS) g_l[i] = b2[i & (N_CLASS - 1)];
}

// ---------------------------------------------------------------------------
// w1t: W1[k][n] fp32 -> g_w1t_{hi,lo}[n][k] bf16    (launch #3)
// ---------------------------------------------------------------------------
__global__ void w1t_kernel(const float* __restrict__ W1) {
    int i = blockIdx.x * blockDim.x + threadIdx.x;
    if (i >= IN_FEAT * HIDDEN) return;
    int k = i >> 6;
    int n = i & 63;
    float v = W1[i];
    __nv_bfloat16 h = __float2bfloat16_rn(v);
    float r = v - __bfloat162float(h);
    g_w1t_hi[(size_t)n * IN_FEAT + k] = h;
    g_w1t_lo[(size_t)n * IN_FEAT + k] = __float2bfloat16_rn(r);
}

// ---------------------------------------------------------------------------
// GEMM1: g_h0 = x @ W1  via mma.sync bf16 (3-term split)   (launch #4)
// CTA: 256 thr = 8 warps. Tile M=64, N=64. grid=782.
// Warp w: row-group (w&3)*16, col-group (w>>2)*32 (4 n-tiles).
// Double-buffered smem (40 KB static) + register prefetch: 1 sync/chunk.
// ---------------------------------------------------------------------------
__global__ __launch_bounds__(256, 3)
void gemm1_kernel(const float* __restrict__ x) {
    __shared__ __align__(16) __nv_bfloat16 Ah[2][RBM * KPAD];     // 2x5 KB
    __shared__ __align__(16) __nv_bfloat16 Al[2][RBM * KPAD];     // 2x5 KB
    __shared__ __align__(16) __nv_bfloat16 Bh[2][HIDDEN * KPAD];  // 2x5 KB
    __shared__ __align__(16) __nv_bfloat16 Bl[2][HIDDEN * KPAD];  // 2x5 KB

    const int tid  = threadIdx.x;
    const int wid  = tid >> 5;
    const int lane = tid & 31;
    const int g    = lane >> 2;       // 0..7
    const int tig  = lane & 3;        // 0..3
    const int rg   = wid & 3;         // row group
    const int cg   = wid >> 2;        // col group
    const int row0 = blockIdx.x * RBM;

    // A staging: 4 threads per row, thread stages 8 k-values (2 float4)
    const int arow = tid >> 2;        // 0..63
    const int aseg = tid & 3;         // 0..3
    int grow = row0 + arow;
    if (grow >= N_NODES) grow = N_NODES - 1;   // clamp; masked at store
    const float* xrow = x + (size_t)grow * IN_FEAT + aseg * 8;

    // B staging: 4 threads per n-row, thread stages 8 bf16 (1 uint4) hi + lo
    const int bn  = tid >> 2;          // 0..63
    const int bsg = tid & 3;           // 0..3

    float4 xr[2];
    uint4  bwh, bwl;

    auto ld = [&](int c) {
        const int k0 = c * KC2;
        xr[0] = __ldg(reinterpret_cast<const float4*>(&xrow[k0]));
        xr[1] = __ldg(reinterpret_cast<const float4*>(&xrow[k0 + 4]));
        bwh = *reinterpret_cast<const uint4*>(
                  &g_w1t_hi[(size_t)bn * IN_FEAT + k0 + bsg * 8]);
        bwl = *reinterpret_cast<const uint4*>(
                  &g_w1t_lo[(size_t)bn * IN_FEAT + k0 + bsg * 8]);
    };
    auto st = [&](int b) {
        #pragma unroll
        for (int q = 0; q < 2; q++) {
            float4 v = xr[q];
            uint2 hv = make_uint2(pack_bf2(v.x, v.y), pack_bf2(v.z, v.w));
            uint2 lv = make_uint2(
                pack_bf2(v.x - bf_round(v.x), v.y - bf_round(v.y)),
                pack_bf2(v.z - bf_round(v.z), v.w - bf_round(v.w)));
            int eo = arow * KPAD + aseg * 8 + q * 4;   // bf16 elements
            *reinterpret_cast<uint2*>(&Ah[b][eo]) = hv;
            *reinterpret_cast<uint2*>(&Al[b][eo]) = lv;
        }
        *reinterpret_cast<uint4*>(&Bh[b][bn * KPAD + bsg * 8]) = bwh;
        *reinterpret_cast<uint4*>(&Bl[b][bn * KPAD + bsg * 8]) = bwl;
    };

    float d[4][4] = {};                // 4 n-tiles x 4 accum

    ld(0); st(0);
    __syncthreads();

    for (int c = 0; c < NCHUNK2; c++) {
        const int cb = c & 1;
        if (c + 1 < NCHUNK2) ld(c + 1);     // LDGs overlap MMA below

        #pragma unroll
        for (int ks = 0; ks < 2; ks++) {
            const int abase = (rg * 16 + g) * KPAD + ks * 16 + 2 * tig;
            uint32_t ah[4], al[4];
            ah[0] = *reinterpret_cast<const uint32_t*>(&Ah[cb][abase]);
            ah[1] = *reinterpret_cast<const uint32_t*>(&Ah[cb][abase + 8 * KPAD]);
            ah[2] = *reinterpret_cast<const uint32_t*>(&Ah[cb][abase + 8]);
            ah[3] = *reinterpret_cast<const uint32_t*>(&Ah[cb][abase + 8 * KPAD + 8]);
            al[0] = *reinterpret_cast<const uint32_t*>(&Al[cb][abase]);
            al[1] = *reinterpret_cast<const uint32_t*>(&Al[cb][abase + 8 * KPAD]);
            al[2] = *reinterpret_cast<const uint32_t*>(&Al[cb][abase + 8]);
            al[3] = *reinterpret_cast<const uint32_t*>(&Al[cb][abase + 8 * KPAD + 8]);
            #pragma unroll
            for (int j = 0; j < 4; j++) {
                const int ntg = cg * 4 + j;
                const int bbase = (ntg * 8 + g) * KPAD + ks * 16 + 2 * tig;
                uint32_t bh0 = *reinterpret_cast<const uint32_t*>(&Bh[cb][bbase]);
                uint32_t bh1 = *reinterpret_cast<const uint32_t*>(&Bh[cb][bbase + 8]);
                uint32_t bl0 = *reinterpret_cast<const uint32_t*>(&Bl[cb][bbase]);
                uint32_t bl1 = *reinterpret_cast<const uint32_t*>(&Bl[cb][bbase + 8]);
                mma_bf16(d[j], ah, bh0, bh1);
                mma_bf16(d[j], al, bh0, bh1);
                mma_bf16(d[j], ah, bl0, bl1);
            }
        }

        if (c + 1 < NCHUNK2) st(1 - cb);     // other buffer: safe pre-sync
        __syncthreads();
    }

    // Epilogue
    {
        int r0 = row0 + rg * 16 + g;
        int r1 = r0 + 8;
        #pragma unroll
        for (int j = 0; j < 4; j++) {
            int col = (cg * 4 + j) * 8 + 2 * tig;
            if (r0 < N_NODES)
                *reinterpret_cast<float2*>(&g_h0[(size_t)r0 * HIDDEN + col]) =
                    make_float2(d[j][0], d[j][1]);
            if (r1 < N_NODES)
                *reinterpret_cast<float2*>(&g_h0[(size_t)r1 * HIDDEN + col]) =
                    make_float2(d[j][2], d[j][3]);
        }
    }
}

// ---------------------------------------------------------------------------
// SpMM1: g_h[dst] += ew * g_h0[src]   (64 feats, 16 lanes/edge, float4 RED)
// ---------------------------------------------------------------------------
__global__ __launch_bounds__(256)
void spmm1_kernel(const int* __restrict__ src, const int* __restrict__ dst,
                  const float* __restrict__ ew) {
    int t = blockIdx.x * blockDim.x + threadIdx.x;
    int e = t >> 4;
    int f = (t & 15) << 2;
    if (e >= N_EDGES) return;
    int s   = __ldg(&src[e]);
    int d   = __ldg(&dst[e]);
    float w = __ldg(&ew[e]);
    float4 v = *reinterpret_cast<const float4*>(&g_h0[(size_t)s * HIDDEN + f]);
    red_add_v4(&g_h[(size_t)d * HIDDEN + f],
               make_float4(v.x * w, v.y * w, v.z * w, v.w * w));
}

// ---------------------------------------------------------------------------
// GEMM2: g_z = relu(g_h) @ W2   (50000x64 @ 64x16), thread per node.
// ---------------------------------------------------------------------------
__global__ __launch_bounds__(64)
void gemm2_kernel(const float* __restrict__ W2) {
    __shared__ float4 Ws[HIDDEN][N_CLASS / 4];   // 4 KB

    const int tid = threadIdx.x;
    #pragma unroll
    for (int j = 0; j < 4; j++) {
        int i = tid + j * 64;
        int kk = i >> 2, qq = i & 3;
        Ws[kk][qq] = reinterpret_cast<const float4*>(&W2[(size_t)kk * N_CLASS])[qq];
    }
    __syncthreads();

    int n = blockIdx.x * 64 + tid;
    if (n >= N_NODES) return;

    float acc[N_CLASS] = {};
    const float4* hrow = reinterpret_cast<const float4*>(&g_h[(size_t)n * HIDDEN]);
    #pragma unroll
    for (int kq = 0; kq < HIDDEN / 4; kq++) {
        float4 h4 = __ldg(&hrow[kq]);
        float hv[4] = {fmaxf(h4.x, 0.f), fmaxf(h4.y, 0.f),
                       fmaxf(h4.z, 0.f), fmaxf(h4.w, 0.f)};
        #pragma unroll
        for (int j = 0; j < 4; j++) {
            int k = kq * 4 + j;
            #pragma unroll
            for (int q = 0; q < 4; q++) {
                float4 w4 = Ws[k][q];
                acc[q * 4 + 0] = fmaf(hv[j], w4.x, acc[q * 4 + 0]);
                acc[q * 4 + 1] = fmaf(hv[j], w4.y, acc[q * 4 + 1]);
                acc[q * 4 + 2] = fmaf(hv[j], w4.z, acc[q * 4 + 2]);
                acc[q * 4 + 3] = fmaf(hv[j], w4.w, acc[q * 4 + 3]);
            }
        }
    }
    float4* o = reinterpret_cast<float4*>(&g_z[(size_t)n * N_CLASS]);
    #pragma unroll
    for (int q = 0; q < 4; q++)
        o[q] = make_float4(acc[q * 4], acc[q * 4 + 1], acc[q * 4 + 2], acc[q * 4 + 3]);
}

// ---------------------------------------------------------------------------
// SpMM2: g_l[dst] += ew * g_z[src]   (16 classes, 4 lanes/edge, float4 RED)
// ---------------------------------------------------------------------------
__global__ __launch_bounds__(256)
void spmm2_kernel(const int* __restrict__ src, const int* __restrict__ dst,
                  const float* __restrict__ ew) {
    int t = blockIdx.x * blockDim.x + threadIdx.x;
    int e = t >> 2;
    int c = (t & 3) << 2;
    if (e >= N_EDGES) return;
    int s   = __ldg(&src[e]);
    int d   = __ldg(&dst[e]);
    float w = __ldg(&ew[e]);
    float4 v = *reinterpret_cast<const float4*>(&g_z[(size_t)s * N_CLASS + c]);
    red_add_v4(&g_l[(size_t)d * N_CLASS + c],
               make_float4(v.x * w, v.y * w, v.z * w, v.w * w));
}

// ---------------------------------------------------------------------------
// Softmax over 16 classes, one thread per node.
// ---------------------------------------------------------------------------
__global__ __launch_bounds__(256)
void softmax_kernel(float* __restrict__ out) {
    int n = blockIdx.x * blockDim.x + threadIdx.x;
    if (n >= N_NODES) return;
    float v[N_CLASS];
    const float4* p = reinterpret_cast<const float4*>(&g_l[(size_t)n * N_CLASS]);
    #pragma unroll
    for (int i = 0; i < 4; i++) {
        float4 q = p[i];
        v[i * 4 + 0] = q.x; v[i * 4 + 1] = q.y; v[i * 4 + 2] = q.z; v[i * 4 + 3] = q.w;
    }
    float m = v[0];
    #pragma unroll
    for (int i = 1; i < N_CLASS; i++) m = fmaxf(m, v[i]);
    float sum = 0.f;
    #pragma unroll
    for (int i = 0; i < N_CLASS; i++) { v[i] = __expf(v[i] - m); sum += v[i]; }
    float inv = 1.f / sum;
    float4* o = reinterpret_cast<float4*>(&out[(size_t)n * N_CLASS]);
    #pragma unroll
    for (int i = 0; i < 4; i++) {
        o[i] = make_float4(v[i * 4] * inv, v[i * 4 + 1] * inv,
                           v[i * 4 + 2] * inv, v[i * 4 + 3] * inv);
    }
}

// ---------------------------------------------------------------------------
extern "C" void kernel_launch(void* const* d_in, const int* in_sizes, int n_in,
                              void* d_out, int out_size) {
    const float* x   = (const float*)d_in[0];
    const int*   src = (const int*)  d_in[1];
    const int*   dst = (const int*)  d_in[2];
    const float* ew  = (const float*)d_in[3];
    const float* W1  = (const float*)d_in[4];
    const float* b1  = (const float*)d_in[5];
    const float* W2  = (const float*)d_in[6];
    const float* b2  = (const float*)d_in[7];
    float* out = (float*)d_out;

    // #1, #2: bias broadcasts
    init_h_kernel<<<(N_NODES * HIDDEN + 255) / 256, 256>>>(b1);
    init_l_kernel<<<(N_NODES * N_CLASS + 255) / 256, 256>>>(b2);
    // #3: W1 transpose + bf16 split
    w1t_kernel<<<(IN_FEAT * HIDDEN + 255) / 256, 256>>>(W1);

    // #4  (profiled slot)
    gemm1_kernel<<<(N_NODES + RBM - 1) / RBM, 256>>>(x);

    // #5
    {
        long long threads = (long long)N_EDGES * 16;
        spmm1_kernel<<<(unsigned)((threads + 255) / 256), 256>>>(src, dst, ew);
    }
    // #6
    gemm2_kernel<<<(N_NODES + 63) / 64, 64>>>(W2);
    // #7
    {
        long long threads = (long long)N_EDGES * 4;
        spmm2_kernel<<<(unsigned)((threads + 255) / 256), 256>>>(src, dst, ew);
    }
    // #8
    softmax_kernel<<<(N_NODES + 255) / 256, 256>>>(out);
}

// round 11
// speedup vs baseline: 1.4015x; 1.0280x over previous
#include <cuda_runtime.h>
#include <cuda_bf16.h>
#include <cstdint>

#define N_NODES 50000
#define N_EDGES 800000
#define IN_FEAT 512
#define HIDDEN  64
#define N_CLASS 16

#define KC2   32                    // K per chunk
#define KPAD  40                    // padded row (80B stride -> conflict-free LDSM)
#define RBM   64                    // rows per CTA in gemm1
#define NCHUNK2 (IN_FEAT / KC2)     // 16

// Scratch (device globals — no allocation allowed)
__device__ float g_h0[N_NODES * HIDDEN];   // x @ W1
__device__ float g_h [N_NODES * HIDDEN];   // A @ h0 + b1 (pre-relu)
__device__ float g_z [N_NODES * N_CLASS];  // relu(h) @ W2
__device__ float g_l [N_NODES * N_CLASS];  // A @ z + b2 (logits)
__device__ __nv_bfloat16 g_w1t_hi[HIDDEN * IN_FEAT];  // W1^T hi, [n][k]
__device__ __nv_bfloat16 g_w1t_lo[HIDDEN * IN_FEAT];  // W1^T residual

__device__ __forceinline__ void red_add_v4(float* p, float4 v) {
    asm volatile("red.global.add.v4.f32 [%0], {%1,%2,%3,%4};"
                 :: "l"(p), "f"(v.x), "f"(v.y), "f"(v.z), "f"(v.w)
                 : "memory");
}

__device__ __forceinline__ uint32_t pack_bf2(float v0, float v1) {
    uint32_t r;
    asm("cvt.rn.bf16x2.f32 %0, %1, %2;" : "=r"(r) : "f"(v1), "f"(v0));
    return r;
}
__device__ __forceinline__ float bf_round(float v) {
    return __bfloat162float(__float2bfloat16_rn(v));
}

__device__ __forceinline__ uint32_t smem_u32(const void* p) {
    uint32_t a;
    asm("{ .reg .u64 t; cvta.to.shared.u64 t, %1; cvt.u32.u64 %0, t; }"
        : "=r"(a) : "l"(p));
    return a;
}

__device__ __forceinline__ void mma_bf16(float* d, const uint32_t* a,
                                         uint32_t b0, uint32_t b1) {
    asm("mma.sync.aligned.m16n8k16.row.col.f32.bf16.bf16.f32 "
        "{%0,%1,%2,%3}, {%4,%5,%6,%7}, {%8,%9}, {%0,%1,%2,%3};"
        : "+f"(d[0]), "+f"(d[1]), "+f"(d[2]), "+f"(d[3])
        : "r"(a[0]), "r"(a[1]), "r"(a[2]), "r"(a[3]), "r"(b0), "r"(b1));
}

#define LDSM4(r0, r1, r2, r3, addr) \
    asm volatile("ldmatrix.sync.aligned.m8n8.x4.shared.b16 {%0,%1,%2,%3}, [%4];" \
                 : "=r"(r0), "=r"(r1), "=r"(r2), "=r"(r3) : "r"(addr))

// ---------------------------------------------------------------------------
// init_h: g_h <- broadcast b1                       (launch #1)
// ---------------------------------------------------------------------------
__global__ void init_h_kernel(const float* __restrict__ b1) {
    int i = blockIdx.x * blockDim.x + threadIdx.x;
    if (i < N_NODES * HIDDEN) g_h[i] = b1[i & (HIDDEN - 1)];
}

// ---------------------------------------------------------------------------
// init_l: g_l <- broadcast b2                       (launch #2)
// ---------------------------------------------------------------------------
__global__ void init_l_kernel(const float* __restrict__ b2) {
    int i = blockIdx.x * blockDim.x + threadIdx.x;
    if (i < N_NODES * N_CLASS) g_l[i] = b2[i & (N_CLASS - 1)];
}

// ---------------------------------------------------------------------------
// w1t: W1[k][n] fp32 -> g_w1t_{hi,lo}[n][k] bf16    (launch #3)
// ---------------------------------------------------------------------------
__global__ void w1t_kernel(const float* __restrict__ W1) {
    int i = blockIdx.x * blockDim.x + threadIdx.x;
    if (i >= IN_FEAT * HIDDEN) return;
    int k = i >> 6;
    int n = i & 63;
    float v = W1[i];
    __nv_bfloat16 h = __float2bfloat16_rn(v);
    float r = v - __bfloat162float(h);
    g_w1t_hi[(size_t)n * IN_FEAT + k] = h;
    g_w1t_lo[(size_t)n * IN_FEAT + k] = __float2bfloat16_rn(r);
}

// ---------------------------------------------------------------------------
// GEMM1: g_h0 = x @ W1  via mma.sync bf16 (3-term split) + ldmatrix  (#4)
// CTA: 256 thr = 8 warps. Tile M=64, N=64. grid=782.
// Warp w: row-group (w&3)*16, col-group (w>>2)*32 (4 n-tiles).
// Double-buffered smem + register prefetch; fragments via LDSM.x4.
// ---------------------------------------------------------------------------
__global__ __launch_bounds__(256, 3)
void gemm1_kernel(const float* __restrict__ x) {
    __shared__ __align__(16) __nv_bfloat16 Ah[2][RBM * KPAD];     // 2x5 KB
    __shared__ __align__(16) __nv_bfloat16 Al[2][RBM * KPAD];     // 2x5 KB
    __shared__ __align__(16) __nv_bfloat16 Bh[2][HIDDEN * KPAD];  // 2x5 KB
    __shared__ __align__(16) __nv_bfloat16 Bl[2][HIDDEN * KPAD];  // 2x5 KB

    const int tid  = threadIdx.x;
    const int wid  = tid >> 5;
    const int lane = tid & 31;
    const int g    = lane >> 2;       // 0..7
    const int tig  = lane & 3;        // 0..3
    const int rg   = wid & 3;         // row group
    const int cg   = wid >> 2;        // col group
    const int row0 = blockIdx.x * RBM;

    // A staging: 4 threads per row, thread stages 8 k-values (2 float4)
    const int arow = tid >> 2;
    const int aseg = tid & 3;
    int grow = row0 + arow;
    if (grow >= N_NODES) grow = N_NODES - 1;   // clamp; masked at store
    const float* xrow = x + (size_t)grow * IN_FEAT + aseg * 8;

    // B staging: 4 threads per n-row, thread stages 8 bf16 hi + lo
    const int bn  = tid >> 2;
    const int bsg = tid & 3;

    // --- LDSM per-lane addresses (byte offsets within buffer 0) ---
    const uint32_t bufStride = RBM * KPAD * 2;   // == HIDDEN*KPAD*2 == 5120
    // A: m0,m1 = rows rg*16+{0-7, 8-15} k0-7; m2,m3 = same rows k8-15
    const int a_row_l = rg * 16 + (lane & 7) + ((lane >> 3) & 1) * 8;
    const int a_koff  = (lane >> 4) * 8;
    const uint32_t aAh = smem_u32(&Ah[0][0]) + (a_row_l * KPAD + a_koff) * 2;
    const uint32_t aAl = smem_u32(&Al[0][0]) + (a_row_l * KPAD + a_koff) * 2;
    // B pair p: m0,m1 = ntile (cg*4+2p) k0-7/k8-15; m2,m3 = ntile (+1)
    uint32_t aBh[2], aBl[2];
    #pragma unroll
    for (int p = 0; p < 2; p++) {
        int nrow = (cg * 4 + 2 * p + (lane >> 4)) * 8 + (lane & 7);
        int koff = ((lane >> 3) & 1) * 8;
        aBh[p] = smem_u32(&Bh[0][0]) + (nrow * KPAD + koff) * 2;
        aBl[p] = smem_u32(&Bl[0][0]) + (nrow * KPAD + koff) * 2;
    }

    float4 xr[2];
    uint4  bwh, bwl;

    auto ld = [&](int c) {
        const int k0 = c * KC2;
        xr[0] = __ldg(reinterpret_cast<const float4*>(&xrow[k0]));
        xr[1] = __ldg(reinterpret_cast<const float4*>(&xrow[k0 + 4]));
        bwh = *reinterpret_cast<const uint4*>(
                  &g_w1t_hi[(size_t)bn * IN_FEAT + k0 + bsg * 8]);
        bwl = *reinterpret_cast<const uint4*>(
                  &g_w1t_lo[(size_t)bn * IN_FEAT + k0 + bsg * 8]);
    };
    auto st = [&](int b) {
        #pragma unroll
        for (int q = 0; q < 2; q++) {
            float4 v = xr[q];
            uint2 hv = make_uint2(pack_bf2(v.x, v.y), pack_bf2(v.z, v.w));
            uint2 lv = make_uint2(
                pack_bf2(v.x - bf_round(v.x), v.y - bf_round(v.y)),
                pack_bf2(v.z - bf_round(v.z), v.w - bf_round(v.w)));
            int eo = arow * KPAD + aseg * 8 + q * 4;
            *reinterpret_cast<uint2*>(&Ah[b][eo]) = hv;
            *reinterpret_cast<uint2*>(&Al[b][eo]) = lv;
        }
        *reinterpret_cast<uint4*>(&Bh[b][bn * KPAD + bsg * 8]) = bwh;
        *reinterpret_cast<uint4*>(&Bl[b][bn * KPAD + bsg * 8]) = bwl;
    };

    float d[4][4] = {};                // 4 n-tiles x 4 accum

    ld(0); st(0);
    __syncthreads();

    for (int c = 0; c < NCHUNK2; c++) {
        const int cb = c & 1;
        const uint32_t bo = cb * bufStride;
        if (c + 1 < NCHUNK2) ld(c + 1);     // LDGs overlap MMA below

        #pragma unroll
        for (int ks = 0; ks < 2; ks++) {
            const uint32_t ko = ks * 32;    // 16 bf16 = 32 bytes
            uint32_t ah[4], al[4];
            LDSM4(ah[0], ah[1], ah[2], ah[3], aAh + bo + ko);
            LDSM4(al[0], al[1], al[2], al[3], aAl + bo + ko);
            #pragma unroll
            for (int p = 0; p < 2; p++) {
                uint32_t bh0, bh1, bh2, bh3, bl0, bl1, bl2, bl3;
                LDSM4(bh0, bh1, bh2, bh3, aBh[p] + bo + ko);
                LDSM4(bl0, bl1, bl2, bl3, aBl[p] + bo + ko);
                mma_bf16(d[2*p],     ah, bh0, bh1);
                mma_bf16(d[2*p],     al, bh0, bh1);
                mma_bf16(d[2*p],     ah, bl0, bl1);
                mma_bf16(d[2*p + 1], ah, bh2, bh3);
                mma_bf16(d[2*p + 1], al, bh2, bh3);
                mma_bf16(d[2*p + 1], ah, bl2, bl3);
            }
        }

        if (c + 1 < NCHUNK2) st(1 - cb);     // other buffer: safe pre-sync
        __syncthreads();
    }

    // Epilogue
    {
        int r0 = row0 + rg * 16 + g;
        int r1 = r0 + 8;
        #pragma unroll
        for (int j = 0; j < 4; j++) {
            int col = (cg * 4 + j) * 8 + 2 * tig;
            if (r0 < N_NODES)
                *reinterpret_cast<float2*>(&g_h0[(size_t)r0 * HIDDEN + col]) =
                    make_float2(d[j][0], d[j][1]);
            if (r1 < N_NODES)
                *reinterpret_cast<float2*>(&g_h0[(size_t)r1 * HIDDEN + col]) =
                    make_float2(d[j][2], d[j][3]);
        }
    }
}

// ---------------------------------------------------------------------------
// SpMM1: g_h[dst] += ew * g_h0[src]   (64 feats, 16 lanes/edge, float4 RED)
// ---------------------------------------------------------------------------
__global__ __launch_bounds__(256)
void spmm1_kernel(const int* __restrict__ src, const int* __restrict__ dst,
                  const float* __restrict__ ew) {
    int t = blockIdx.x * blockDim.x + threadIdx.x;
    int e = t >> 4;
    int f = (t & 15) << 2;
    if (e >= N_EDGES) return;
    int s   = __ldg(&src[e]);
    int d   = __ldg(&dst[e]);
    float w = __ldg(&ew[e]);
    float4 v = *reinterpret_cast<const float4*>(&g_h0[(size_t)s * HIDDEN + f]);
    red_add_v4(&g_h[(size_t)d * HIDDEN + f],
               make_float4(v.x * w, v.y * w, v.z * w, v.w * w));
}

// ---------------------------------------------------------------------------
// GEMM2: g_z = relu(g_h) @ W2   (50000x64 @ 64x16), thread per node.
// ---------------------------------------------------------------------------
__global__ __launch_bounds__(64)
void gemm2_kernel(const float* __restrict__ W2) {
    __shared__ float4 Ws[HIDDEN][N_CLASS / 4];   // 4 KB

    const int tid = threadIdx.x;
    #pragma unroll
    for (int j = 0; j < 4; j++) {
        int i = tid + j * 64;
        int kk = i >> 2, qq = i & 3;
        Ws[kk][qq] = reinterpret_cast<const float4*>(&W2[(size_t)kk * N_CLASS])[qq];
    }
    __syncthreads();

    int n = blockIdx.x * 64 + tid;
    if (n >= N_NODES) return;

    float acc[N_CLASS] = {};
    const float4* hrow = reinterpret_cast<const float4*>(&g_h[(size_t)n * HIDDEN]);
    #pragma unroll
    for (int kq = 0; kq < HIDDEN / 4; kq++) {
        float4 h4 = __ldg(&hrow[kq]);
        float hv[4] = {fmaxf(h4.x, 0.f), fmaxf(h4.y, 0.f),
                       fmaxf(h4.z, 0.f), fmaxf(h4.w, 0.f)};
        #pragma unroll
        for (int j = 0; j < 4; j++) {
            int k = kq * 4 + j;
            #pragma unroll
            for (int q = 0; q < 4; q++) {
                float4 w4 = Ws[k][q];
                acc[q * 4 + 0] = fmaf(hv[j], w4.x, acc[q * 4 + 0]);
                acc[q * 4 + 1] = fmaf(hv[j], w4.y, acc[q * 4 + 1]);
                acc[q * 4 + 2] = fmaf(hv[j], w4.z, acc[q * 4 + 2]);
                acc[q * 4 + 3] = fmaf(hv[j], w4.w, acc[q * 4 + 3]);
            }
        }
    }
    float4* o = reinterpret_cast<float4*>(&g_z[(size_t)n * N_CLASS]);
    #pragma unroll
    for (int q = 0; q < 4; q++)
        o[q] = make_float4(acc[q * 4], acc[q * 4 + 1], acc[q * 4 + 2], acc[q * 4 + 3]);
}

// ---------------------------------------------------------------------------
// SpMM2: g_l[dst] += ew * g_z[src]   (16 classes, 4 lanes/edge, float4 RED)
// ---------------------------------------------------------------------------
__global__ __launch_bounds__(256)
void spmm2_kernel(const int* __restrict__ src, const int* __restrict__ dst,
                  const float* __restrict__ ew) {
    int t = blockIdx.x * blockDim.x + threadIdx.x;
    int e = t >> 2;
    int c = (t & 3) << 2;
    if (e >= N_EDGES) return;
    int s   = __ldg(&src[e]);
    int d   = __ldg(&dst[e]);
    float w = __ldg(&ew[e]);
    float4 v = *reinterpret_cast<const float4*>(&g_z[(size_t)s * N_CLASS + c]);
    red_add_v4(&g_l[(size_t)d * N_CLASS + c],
               make_float4(v.x * w, v.y * w, v.z * w, v.w * w));
}

// ---------------------------------------------------------------------------
// Softmax over 16 classes, one thread per node.
// ---------------------------------------------------------------------------
__global__ __launch_bounds__(256)
void softmax_kernel(float* __restrict__ out) {
    int n = blockIdx.x * blockDim.x + threadIdx.x;
    if (n >= N_NODES) return;
    float v[N_CLASS];
    const float4* p = reinterpret_cast<const float4*>(&g_l[(size_t)n * N_CLASS]);
    #pragma unroll
    for (int i = 0; i < 4; i++) {
        float4 q = p[i];
        v[i * 4 + 0] = q.x; v[i * 4 + 1] = q.y; v[i * 4 + 2] = q.z; v[i * 4 + 3] = q.w;
    }
    float m = v[0];
    #pragma unroll
    for (int i = 1; i < N_CLASS; i++) m = fmaxf(m, v[i]);
    float sum = 0.f;
    #pragma unroll
    for (int i = 0; i < N_CLASS; i++) { v[i] = __expf(v[i] - m); sum += v[i]; }
    float inv = 1.f / sum;
    float4* o = reinterpret_cast<float4*>(&out[(size_t)n * N_CLASS]);
    #pragma unroll
    for (int i = 0; i < 4; i++) {
        o[i] = make_float4(v[i * 4] * inv, v[i * 4 + 1] * inv,
                           v[i * 4 + 2] * inv, v[i * 4 + 3] * inv);
    }
}

// ---------------------------------------------------------------------------
extern "C" void kernel_launch(void* const* d_in, const int* in_sizes, int n_in,
                              void* d_out, int out_size) {
    const float* x   = (const float*)d_in[0];
    const int*   src = (const int*)  d_in[1];
    const int*   dst = (const int*)  d_in[2];
    const float* ew  = (const float*)d_in[3];
    const float* W1  = (const float*)d_in[4];
    const float* b1  = (const float*)d_in[5];
    const float* W2  = (const float*)d_in[6];
    const float* b2  = (const float*)d_in[7];
    float* out = (float*)d_out;

    // #1, #2: bias broadcasts
    init_h_kernel<<<(N_NODES * HIDDEN + 255) / 256, 256>>>(b1);
    init_l_kernel<<<(N_NODES * N_CLASS + 255) / 256, 256>>>(b2);
    // #3: W1 transpose + bf16 split
    w1t_kernel<<<(IN_FEAT * HIDDEN + 255) / 256, 256>>>(W1);

    // #4  (profiled slot)
    gemm1_kernel<<<(N_NODES + RBM - 1) / RBM, 256>>>(x);

    // #5
    {
        long long threads = (long long)N_EDGES * 16;
        spmm1_kernel<<<(unsigned)((threads + 255) / 256), 256>>>(src, dst, ew);
    }
    // #6
    gemm2_kernel<<<(N_NODES + 63) / 64, 64>>>(W2);
    // #7
    {
        long long threads = (long long)N_EDGES * 4;
        spmm2_kernel<<<(unsigned)((threads + 255) / 256), 256>>>(src, dst, ew);
    }
    // #8
    softmax_kernel<<<(N_NODES + 255) / 256, 256>>>(out);
}